// round 10
// baseline (speedup 1.0000x reference)
#include <cuda_runtime.h>
#include <cstdint>

#define BATCH       64
#define SIZE        224
#define PIXELS      (SIZE*SIZE)        // 50176
#define DIM         40
#define NUM_CLASSES 10
#define WORDS       (PIXELS/32)        // 1568
#define NCHUNK      28                 // word chunks in main kernel
#define CW          (WORDS/NCHUNK)     // 56 words per chunk (exact)
#define QPITCH      57                 // gcd(57,32)=1 -> conflict-free strides
#define BPB         4                  // batches per main block
#define PPB         128                // pixels per pack block
#define NBP         (PIXELS/PPB)       // 392 pack blocks

// Packed pos sign bits per dim + deterministic partial accumulators
// (every slot written every launch -> no zeroing, no global atomics).
__device__ uint32_t g_Q[DIM * WORDS];              // 251 KB
__device__ int      g_TotPart[NCHUNK * DIM];       // popc(Q) per (chunk,d)
__device__ int      g_Part[NCHUNK * BATCH * DIM];  // AND-popc per (chunk,b,d)
__device__ int      g_CPart[NCHUNK * BATCH];       // popc(M) per (chunk,b)

// ---------------------------------------------------------------------------
// Kernel A (pack v4): 392 blocks x 128 pixels, 320 threads = 8 px x 40 dims.
// 16 independent coalesced loads/thread (deep MLP), fixed-increment indexing,
// warp packs 4 dims x 4 words -> one STG.128 per dim.
// Exactness: pos/level are exactly {-1,+1}; NUM_LEVELS=2 -> idx=round(x) with
// half-to-even so level-1 <=> x>0.5 strictly. All sums to `enc` are exact
// integers in both this kernel and the reference fp32 math.
// ---------------------------------------------------------------------------
__global__ void __launch_bounds__(320)
pack_pos_kernel(const float* __restrict__ pos) {
    __shared__ float tile[PPB * 41];          // 21 KB, pitch 41
    const int tid  = threadIdx.x;
    const int lane = tid & 31;
    const int wid  = tid >> 5;                // 10 warps
    const int p0   = blockIdx.x * PPB;

    // Phase 1: 16 iters x 320 threads = 5120 floats, fully coalesced.
    const int p = tid / DIM;                  // once
    const int d = tid - p * DIM;              // once
    const float* __restrict__ src = pos + (size_t)(p0 + p) * DIM + d;
    float* dst = &tile[p * 41 + d];
    #pragma unroll
    for (int k = 0; k < PPB / 8; k++)
        dst[k * (8 * 41)] = src[k * (8 * DIM)];   // addr = fixed increments
    __syncthreads();

    // Phase 2: warp 'wid' packs dims [wid*4, wid*4+4), 4 words each, STG.128.
    #pragma unroll
    for (int k = 0; k < 4; k++) {
        int dd = wid * 4 + k;
        unsigned q0 = __ballot_sync(0xffffffffu, tile[lane * 41 + dd]        > 0.0f);
        unsigned q1 = __ballot_sync(0xffffffffu, tile[(32 + lane) * 41 + dd] > 0.0f);
        unsigned q2 = __ballot_sync(0xffffffffu, tile[(64 + lane) * 41 + dd] > 0.0f);
        unsigned q3 = __ballot_sync(0xffffffffu, tile[(96 + lane) * 41 + dd] > 0.0f);
        if (lane == 0)   // p0/32 is a multiple of 4 -> 16B-aligned
            *reinterpret_cast<uint4*>(&g_Q[dd * WORDS + (p0 >> 5)]) =
                make_uint4(q0, q1, q2, q3);
    }
}

// ---------------------------------------------------------------------------
// Kernel B: block = (chunk c, batch-quad) -> 4 batches share the staged Q
// chunk (Q re-staging 4 MB total). uint4 staging. Per-lane dim accumulators;
// the 28 quad==0 blocks also emit Tot partials from resident sQ.
// ---------------------------------------------------------------------------
__global__ void __launch_bounds__(256)
main_kernel(const float* __restrict__ x) {
    const int c  = blockIdx.x >> 4;       // 0..27 (same-chunk blocks adjacent)
    const int bq = blockIdx.x & 15;
    const int b0 = bq * BPB;
    const int tid  = threadIdx.x;
    const int lane = tid & 31;
    const int wid  = tid >> 5;            // 8 warps

    __shared__ uint32_t sQ[DIM * QPITCH];     // 9.1 KB
    __shared__ int sAcc[BPB][DIM];
    __shared__ int sC[BPB];

    if (tid < DIM) {
        #pragma unroll
        for (int i = 0; i < BPB; i++) sAcc[i][tid] = 0;
    }
    if (tid < BPB) sC[tid] = 0;

    const int w0 = c * CW;
    // Stage Q chunk: 40 dims x 14 uint4 = 560 vec loads.
    for (int i = tid; i < DIM * (CW / 4); i += 256) {
        int d = i / (CW / 4), j4 = i - d * (CW / 4);
        uint4 v = *reinterpret_cast<const uint4*>(&g_Q[d * WORDS + w0 + j4 * 4]);
        uint32_t* q = &sQ[d * QPITCH + j4 * 4];
        q[0] = v.x; q[1] = v.y; q[2] = v.z; q[3] = v.w;
    }
    __syncthreads();

    // Warp 'wid' covers words [wid*7, wid*7+7) of this chunk, 4 batches.
    const float* __restrict__ xb0 = x + (size_t)b0 * PIXELS + (size_t)w0 * 32;
    const int jbase = wid * (CW / 8);                  // 7 words/warp
    int aLo[BPB] = {0, 0, 0, 0};                       // dim = lane
    int aHi[BPB] = {0, 0, 0, 0};                       // dims 32..39 (lane<8)
    int cc[BPB]  = {0, 0, 0, 0};
    #pragma unroll
    for (int jj = 0; jj < CW / 8; jj++) {
        int j = jbase + jj;
        unsigned m[BPB];
        #pragma unroll
        for (int i = 0; i < BPB; i++) {
            float v = xb0[(size_t)i * PIXELS + j * 32 + lane];  // 128B coalesced
            m[i] = __ballot_sync(0xffffffffu, v > 0.5f);
            cc[i] += __popc(m[i]);
        }
        uint32_t q0 = sQ[lane * QPITCH + j];
        #pragma unroll
        for (int i = 0; i < BPB; i++) aLo[i] += __popc(m[i] & q0);
        if (lane < 8) {
            uint32_t q1 = sQ[(lane + 32) * QPITCH + j];
            #pragma unroll
            for (int i = 0; i < BPB; i++) aHi[i] += __popc(m[i] & q1);
        }
    }
    #pragma unroll
    for (int i = 0; i < BPB; i++) {
        atomicAdd(&sAcc[i][lane], aLo[i]);
        if (lane < 8) atomicAdd(&sAcc[i][lane + 32], aHi[i]);
        if (lane == 0) atomicAdd(&sC[i], cc[i]);
    }

    // Tot partials: the 28 bq==0 blocks popc their resident sQ chunk.
    if (bq == 0) {
        #pragma unroll
        for (int k = 0; k < DIM / 8; k++) {
            int d = wid + 8 * k;
            int t = 0;
            for (int j = lane; j < CW; j += 32)        // 1-2 words/lane
                t += __popc(sQ[d * QPITCH + j]);
            t = __reduce_add_sync(0xffffffffu, t);
            if (lane == 0) g_TotPart[c * DIM + d] = t;
        }
    }
    __syncthreads();

    if (tid < DIM) {
        #pragma unroll
        for (int i = 0; i < BPB; i++)
            g_Part[(c * BATCH + b0 + i) * DIM + tid] = sAcc[i][tid];
    }
    if (tid < BPB) g_CPart[c * BATCH + b0 + tid] = sC[tid];
}

// ---------------------------------------------------------------------------
// Kernel C: 64 blocks (one per batch). Chunk-sum + exact integer epilogue +
// sign + classify.
// ---------------------------------------------------------------------------
__global__ void __launch_bounds__(64)
epilogue_kernel(const float* __restrict__ lvl,   // [2, DIM]
                const float* __restrict__ cls,   // [10, DIM]
                float* __restrict__ out) {       // [BATCH, 10]
    const int b   = blockIdx.x;
    const int tid = threadIdx.x;
    __shared__ float enc[DIM];
    __shared__ int   sCsum;

    if (tid == 0) {
        int s = 0;
        #pragma unroll
        for (int c = 0; c < NCHUNK; c++) s += g_CPart[c * BATCH + b];
        sCsum = s;
    }
    __syncthreads();

    if (tid < DIM) {
        int sA = 0, sT = 0;
        #pragma unroll
        for (int c = 0; c < NCHUNK; c++) {
            sA += g_Part[(c * BATCH + b) * DIM + tid];
            sT += g_TotPart[c * DIM + tid];
        }
        int A   = 2 * sA - sCsum;           // sum of pos over masked pixels
        int Tot = 2 * sT - PIXELS;          // sum of pos over all pixels
        float summed = lvl[tid] * (float)(Tot - A) + lvl[DIM + tid] * (float)A;
        enc[tid] = (summed > 0.0f) ? 1.0f : -1.0f;
    }
    __syncthreads();

    if (tid < NUM_CLASSES) {
        float acc = 0.0f;
        #pragma unroll
        for (int d = 0; d < DIM; d++) acc += enc[d] * cls[tid * DIM + d];
        out[b * NUM_CLASSES + tid] = acc;
    }
}

// ---------------------------------------------------------------------------
extern "C" void kernel_launch(void* const* d_in, const int* in_sizes, int n_in,
                              void* d_out, int out_size) {
    const float* x   = (const float*)d_in[0];   // [64, 224, 224]
    const float* pos = (const float*)d_in[1];   // [50176, 40]
    const float* lvl = (const float*)d_in[2];   // [2, 40]
    const float* cls = (const float*)d_in[3];   // [10, 40]
    float* out = (float*)d_out;                 // [64, 10]

    pack_pos_kernel<<<NBP, 320>>>(pos);
    main_kernel<<<NCHUNK * (BATCH / BPB), 256>>>(x);
    epilogue_kernel<<<BATCH, 64>>>(lvl, cls, out);
}